// round 11
// baseline (speedup 1.0000x reference)
#include <cuda_runtime.h>

// PManifold via moment factorization.
// f(u) = 1 + u/3 + u^2/5 + u^3/7 (deg-3 atanh-series, validated R9/R10: 1.61e-5).
// u = ps_r + c_q + alpha_q*p0_r + beta_q*p1_r  (c = ||theta||^2 + 1e-12, alpha = 2*theta0, beta = 2*theta1)
// Multinomial expansion separates (q) from (r):
//   F_q     = sum_t W_t(q) * M[a_t,e_t,h_t]      (20 tuples, a+e+h<=3)
//   s[d]    = sum_t M_t * Abar[t][d],  Abar[t][d] = sum_q W_t(q) theta_qd   (per-slot const)
//   G0/G1   = sum_t M[a,e+1,h]/M[a,e,h+1] * B[t], B[t] = sum_q W_t(q)
// K1 precomputes the coefficient table gC[slot][38 moment-slots][12 jobs] (zero-padded);
// K2 computes 33 point-monomials per output, reduces, and does uniform 38-long dots.
// Epilogue (validated R9): out = (2/(1-float32(0.99999))) * s/||s|| = 199728.765625 * s-hat.

#define PB 32
#define PSLOTS 2
#define PN 1024
#define PK 64
#define PD 10
#define OS_CONST 199728.765625f

// ---- tuple tables: t=0..19, (a,e,h) with a+e+h<=3 ----
// order: (000) (100)(010)(001) (200)(110)(101)(020)(011)(002)
//        (300)(210)(201)(120)(111)(102)(030)(021)(012)(003)
__constant__ int cE[20] = {0, 0,1,0, 0,1,0,2,1,0, 0,1,0,2,1,0,3,2,1,0};
__constant__ int cH[20] = {0, 0,0,1, 0,0,1,0,1,2, 0,0,1,0,1,2,0,1,2,3};
// K_t(c) = k0 + k1 c + k2 c^2 + k3 c^3  (from g_k * multinomial coefficients)
__constant__ float cK0[20] = {1.0f, 1.0f/3,1.0f/3,1.0f/3, 0.2f,0.4f,0.4f,0.2f,0.4f,0.2f,
                              1.0f/7,3.0f/7,3.0f/7,3.0f/7,6.0f/7,3.0f/7,1.0f/7,3.0f/7,3.0f/7,1.0f/7};
__constant__ float cK1[20] = {1.0f/3, 0.4f,0.4f,0.4f, 3.0f/7,6.0f/7,6.0f/7,3.0f/7,6.0f/7,3.0f/7,
                              0,0,0,0,0,0,0,0,0,0};
__constant__ float cK2[20] = {0.2f, 3.0f/7,3.0f/7,3.0f/7, 0,0,0,0,0,0, 0,0,0,0,0,0,0,0,0,0};
__constant__ float cK3[20] = {1.0f/7, 0,0,0, 0,0,0,0,0,0, 0,0,0,0,0,0,0,0,0,0};
// smem moment-slot of tuple t's base moment (t=0 -> slot 37 = constant 16)
__constant__ int cSOff[20] = {37, 0,1,2, 3,4,5,6,7,8, 10,11,12,13,14,15,16,17, 20,21};
// slot of M[a,e+1,h] (G0) and M[a,e,h+1] (G1) per tuple
__constant__ int cG0[20] = {1,4,6,7, 11,13,14,16,17,20, 22,23,24,25,26,27,28,30,31,32};
__constant__ int cG1[20] = {2,5,7,8, 12,14,15,17,20,21, 33,24,34,26,27,35,30,31,32,36};

// zero-initialized coefficient table; unwritten slots stay 0 (used as padding)
__device__ float gC[PSLOTS][38][12];

// ================= K1: coefficient precompute (440 warps) =================
__global__ void pman_coef_kernel(const float* __restrict__ theta) {
    const int w    = blockIdx.x * 4 + (threadIdx.x >> 5);   // 0..439
    const int lane = threadIdx.x & 31;
    const int slot = w / 220;
    const int rem  = w % 220;
    const int t    = rem / 11;
    const int col  = rem % 11;          // 0..9: Abar[t][col]; 10: B[t]

    const float* th = theta + (size_t)slot * PK * PD;
    const int e = cE[t], hh = cH[t];
    const float k0 = cK0[t], k1 = cK1[t], k2 = cK2[t], k3 = cK3[t];

    float acc = 0.0f;
    #pragma unroll
    for (int half = 0; half < 2; ++half) {
        const int q = lane + half * 32;
        const float2* row = reinterpret_cast<const float2*>(th + q * PD);
        float c = 1e-12f;
        float t0v = 0.0f, t1v = 0.0f;
        #pragma unroll
        for (int i = 0; i < 5; ++i) {
            float2 v = row[i];
            if (i == 0) { t0v = v.x; t1v = v.y; }
            c = fmaf(v.x, v.x, c);
            c = fmaf(v.y, v.y, c);
        }
        float K = fmaf(fmaf(fmaf(k3, c, k2), c, k1), c, k0);
        const float al = 2.0f * t0v, be = 2.0f * t1v;
        for (int i = 0; i < e;  ++i) K *= al;   // uniform per warp
        for (int i = 0; i < hh; ++i) K *= be;
        const float td = (col < 10) ? th[q * PD + col] : 1.0f;
        acc = fmaf(K, td, acc);
    }
    #pragma unroll
    for (int off = 16; off > 0; off >>= 1)
        acc += __shfl_xor_sync(0xffffffffu, acc, off);

    if (lane == 0) {
        if (col < 10) {
            gC[slot][cSOff[t]][col] = acc;
        } else {
            gC[slot][cG0[t]][10] = acc;   // B[t] feeds both G columns
            gC[slot][cG1[t]][11] = acc;
        }
    }
}

// ================= K2: main kernel (half-warp per output) =================
__global__ __launch_bounds__(128, 4) void pman_main_kernel(
    const float* __restrict__ inp,    // [32, 2, 1024, 2]
    float* __restrict__ out)          // [32, 2, 64, 10]
{
    __shared__ float sC[38 * 12];     // this slot's coefficient table
    __shared__ float sMom[8][40];     // per-kk moment slots
    __shared__ float sS[8][12];       // per-kk job results

    const int b    = blockIdx.z;
    const int slot = blockIdx.y;
    const int bx   = blockIdx.x;
    const int tid  = threadIdx.x;
    const int warp = tid >> 5;
    const int lane = tid & 31;
    const int Hh   = (lane >> 4) & 1;           // half-warp id
    const int kkL  = warp * 2 + Hh;             // 0..7
    const int kk   = bx * 8 + kkL;
    const int l    = lane & 15;                 // point index r within kk

    // ---- stage coefficient table (456 floats) ----
    const float* gCs = &gC[slot][0][0];
    #pragma unroll
    for (int i = tid; i < 38 * 12; i += 128) sC[i] = gCs[i];

    // ---- load point r=l, param() ----
    const float2 pt = reinterpret_cast<const float2*>(
        inp + (size_t)(b * PSLOTS + slot) * PN * 2)[l * PK + kk];
    const float q2 = fmaf(pt.x, pt.x, pt.y * pt.y);
    const float rr = 1.0f / (1.0f + sqrtf(1.0f + q2));
    const float p0 = pt.x * rr;
    const float p1 = pt.y * rr;
    const float ps = fmaf(p0, p0, p1 * p1);

    // ---- 33 monomials ps^a p0^e p1^h ----
    const float ps2 = ps * ps, ps3 = ps2 * ps;
    const float a2 = p0 * p0, a3 = a2 * p0, a4 = a2 * a2;
    const float b2 = p1 * p1, b3v = b2 * p1, b4 = b2 * b2;
    const float ab = p0 * p1;
    float v[34];
    v[0] = ps;        v[1] = p0;        v[2] = p1;
    v[3] = ps2;       v[4] = ps * p0;   v[5] = ps * p1;
    v[6] = a2;        v[7] = ab;        v[8] = b2;
    v[9] = ps3;       v[10] = ps2 * p0; v[11] = ps2 * p1;
    v[12] = ps * a2;  v[13] = ps * ab;  v[14] = ps * b2;
    v[15] = a3;       v[16] = a2 * p1;  v[17] = p0 * b2;  v[18] = b3v;
    v[19] = ps3 * p0; v[20] = ps2 * a2; v[21] = ps2 * ab;
    v[22] = ps * a3;  v[23] = ps * v[16]; v[24] = ps * v[17];
    v[25] = a4;       v[26] = a3 * p1;  v[27] = a2 * b2;  v[28] = p0 * b3v;
    v[29] = ps3 * p1; v[30] = ps2 * b2; v[31] = ps * b3v; v[32] = b4;
    v[33] = 0.0f;     // pad

    // ---- split-shuffle reduction over the 16-lane half-warp ----
    // L8: 34 -> 17 (lo keeps [0..16], hi keeps [17..33])
    float w8[18];
    #pragma unroll
    for (int k = 0; k < 17; ++k) {
        const float send = (lane & 8) ? v[k] : v[17 + k];
        const float recv = __shfl_xor_sync(0xffffffffu, send, 8);
        w8[k] = ((lane & 8) ? v[17 + k] : v[k]) + recv;
    }
    w8[17] = 0.0f;
    // L4: 17(+pad) -> 9
    float x4[10];
    #pragma unroll
    for (int k = 0; k < 9; ++k) {
        const float send = (lane & 4) ? w8[k] : w8[9 + k];
        const float recv = __shfl_xor_sync(0xffffffffu, send, 4);
        x4[k] = ((lane & 4) ? w8[9 + k] : w8[k]) + recv;
    }
    x4[9] = 0.0f;
    // L2: 9(+pad) -> 5
    float z5[5];
    #pragma unroll
    for (int k = 0; k < 5; ++k) {
        const float send = (lane & 2) ? x4[k] : x4[5 + k];
        const float recv = __shfl_xor_sync(0xffffffffu, send, 2);
        z5[k] = ((lane & 2) ? x4[5 + k] : x4[k]) + recv;
    }
    // L1: full sum
    #pragma unroll
    for (int k = 0; k < 5; ++k)
        z5[k] += __shfl_xor_sync(0xffffffffu, z5[k], 1);

    // ---- store moments: lane pattern (b3,b2,b1) -> slot base 20*b3+10*b2+5*b1 ----
    if (!(lane & 1)) {
        const int base = ((lane >> 1) & 7) * 5;
        #pragma unroll
        for (int k = 0; k < 5; ++k) {
            float val = z5[k];
            if (base + k == 37) val = 16.0f;   // constant moment M[0,0,0]
            sMom[kkL][base + k] = val;
        }
    }
    __syncthreads();   // orders sC staging + sMom stores before matvec

    // ---- uniform matvec: 12 jobs (10 dims + G0 + G1), 38-long dots ----
    const int j = lane & 15;
    if (j < 12) {
        float acc = 0.0f;
        #pragma unroll
        for (int ms = 0; ms < 38; ++ms)
            acc = fmaf(sMom[kkL][ms], sC[ms * 12 + j], acc);
        sS[kkL][j] = acc;
    }
    __syncwarp();

    // ---- epilogue: out = OS_CONST * s / ||s|| ----
    if ((lane & 15) == 0) {
        const float* sv = sS[kkL];
        const float s0 = sv[0] + sv[10];
        const float s1 = sv[1] + sv[11];
        float dot = fmaf(s0, s0, s1 * s1);
        #pragma unroll
        for (int d = 2; d < 10; ++d)
            dot = fmaf(sv[d], sv[d], dot);
        const float cm = OS_CONST * rsqrtf(dot);

        float* op = out + (size_t)((b * PSLOTS + slot) * PK + kk) * PD;
        float2* o2 = reinterpret_cast<float2*>(op);
        o2[0] = make_float2(cm * s0,    cm * s1);
        o2[1] = make_float2(cm * sv[2], cm * sv[3]);
        o2[2] = make_float2(cm * sv[4], cm * sv[5]);
        o2[3] = make_float2(cm * sv[6], cm * sv[7]);
        o2[4] = make_float2(cm * sv[8], cm * sv[9]);
    }
}

extern "C" void kernel_launch(void* const* d_in, const int* in_sizes, int n_in,
                              void* d_out, int out_size) {
    const float* inp   = (const float*)d_in[0];
    const float* theta = (const float*)d_in[1];
    if (n_in >= 2 && in_sizes[0] == PSLOTS * PK * PD) {
        inp   = (const float*)d_in[1];
        theta = (const float*)d_in[0];
    }
    float* out = (float*)d_out;

    pman_coef_kernel<<<110, 128>>>(theta);          // 440 warps
    dim3 grid(8, PSLOTS, PB);                       // 512 blocks
    pman_main_kernel<<<grid, 128>>>(inp, out);
}

// round 12
// speedup vs baseline: 1.0684x; 1.0684x over previous
#include <cuda_runtime.h>

// PManifold via moment factorization + PDL overlap.
// f(u) = 1 + u/3 + u^2/5 + u^3/7 (deg-3 atanh series; rel_err 1.62e-5, tol 1e-3).
// K1 builds gC[slot][38][12] (q-summed coefficient table) from theta.
// K2 computes 33 point-monomials/output, half-warp reduction, then a 38x12 matvec
// against gC and the saturation epilogue out = 199728.765625 * s/||s||.
// K2 is launched with Programmatic Stream Serialization: its front phase (point
// loads, monomials, reduction) overlaps K1; cudaGridDependencySynchronize() gates
// only the gC reads. No __syncthreads anywhere in K2 (all exchanges warp-local).

#define PB 32
#define PSLOTS 2
#define PN 1024
#define PK 64
#define PD 10
#define OS_CONST 199728.765625f   // 2 / (1 - float32(0.99999)) = 2^25/168

// ---- tuple tables: t=0..19, (a,e,h) with a+e+h<=3 ----
__constant__ int cE[20] = {0, 0,1,0, 0,1,0,2,1,0, 0,1,0,2,1,0,3,2,1,0};
__constant__ int cH[20] = {0, 0,0,1, 0,0,1,0,1,2, 0,0,1,0,1,2,0,1,2,3};
__constant__ float cK0[20] = {1.0f, 1.0f/3,1.0f/3,1.0f/3, 0.2f,0.4f,0.4f,0.2f,0.4f,0.2f,
                              1.0f/7,3.0f/7,3.0f/7,3.0f/7,6.0f/7,3.0f/7,1.0f/7,3.0f/7,3.0f/7,1.0f/7};
__constant__ float cK1[20] = {1.0f/3, 0.4f,0.4f,0.4f, 3.0f/7,6.0f/7,6.0f/7,3.0f/7,6.0f/7,3.0f/7,
                              0,0,0,0,0,0,0,0,0,0};
__constant__ float cK2[20] = {0.2f, 3.0f/7,3.0f/7,3.0f/7, 0,0,0,0,0,0, 0,0,0,0,0,0,0,0,0,0};
__constant__ float cK3[20] = {1.0f/7, 0,0,0, 0,0,0,0,0,0, 0,0,0,0,0,0,0,0,0,0};
__constant__ int cSOff[20] = {37, 0,1,2, 3,4,5,6,7,8, 10,11,12,13,14,15,16,17, 20,21};
__constant__ int cG0[20] = {1,4,6,7, 11,13,14,16,17,20, 22,23,24,25,26,27,28,30,31,32};
__constant__ int cG1[20] = {2,5,7,8, 12,14,15,17,20,21, 33,24,34,26,27,35,30,31,32,36};

// zero-initialized coefficient table; unwritten slots stay 0 (padding)
__device__ float gC[PSLOTS][38][12];

// ================= K1: coefficient precompute (440 warps) =================
__global__ void pman_coef_kernel(const float* __restrict__ theta) {
    const int w    = blockIdx.x * 4 + (threadIdx.x >> 5);   // 0..439
    const int lane = threadIdx.x & 31;
    const int slot = w / 220;
    const int rem  = w % 220;
    const int t    = rem / 11;
    const int col  = rem % 11;          // 0..9: Abar[t][col]; 10: B[t]

    const float* th = theta + (size_t)slot * PK * PD;
    const int e = cE[t], hh = cH[t];
    const float k0 = cK0[t], k1 = cK1[t], k2 = cK2[t], k3 = cK3[t];

    float acc = 0.0f;
    #pragma unroll
    for (int half = 0; half < 2; ++half) {
        const int q = lane + half * 32;
        const float2* row = reinterpret_cast<const float2*>(th + q * PD);
        float c = 1e-12f;
        float t0v = 0.0f, t1v = 0.0f;
        #pragma unroll
        for (int i = 0; i < 5; ++i) {
            float2 v = row[i];
            if (i == 0) { t0v = v.x; t1v = v.y; }
            c = fmaf(v.x, v.x, c);
            c = fmaf(v.y, v.y, c);
        }
        float K = fmaf(fmaf(fmaf(k3, c, k2), c, k1), c, k0);
        const float al = 2.0f * t0v, be = 2.0f * t1v;
        for (int i = 0; i < e;  ++i) K *= al;
        for (int i = 0; i < hh; ++i) K *= be;
        const float td = (col < 10) ? th[q * PD + col] : 1.0f;
        acc = fmaf(K, td, acc);
    }
    #pragma unroll
    for (int off = 16; off > 0; off >>= 1)
        acc += __shfl_xor_sync(0xffffffffu, acc, off);

    if (lane == 0) {
        if (col < 10) {
            gC[slot][cSOff[t]][col] = acc;
        } else {
            gC[slot][cG0[t]][10] = acc;
            gC[slot][cG1[t]][11] = acc;
        }
    }
#if __CUDA_ARCH__ >= 900
    cudaTriggerProgrammaticLaunchCompletion();
#endif
}

// ================= K2: main kernel (half-warp per output) =================
__global__ __launch_bounds__(128, 4) void pman_main_kernel(
    const float* __restrict__ inp,    // [32, 2, 1024, 2]
    float* __restrict__ out)          // [32, 2, 64, 10]
{
    __shared__ float sMom[8][40];     // per-kk moment slots (warp-local use)
    __shared__ float sS[8][12];       // per-kk job results   (warp-local use)

    const int b    = blockIdx.z;
    const int slot = blockIdx.y;
    const int bx   = blockIdx.x;
    const int tid  = threadIdx.x;
    const int warp = tid >> 5;
    const int lane = tid & 31;
    const int Hh   = (lane >> 4) & 1;           // half-warp id
    const int kkL  = warp * 2 + Hh;             // 0..7
    const int kk   = bx * 8 + kkL;
    const int l    = lane & 15;                 // point index r within kk

    // ---- front phase (independent of K1): load point, param(), monomials ----
    const float2 pt = reinterpret_cast<const float2*>(
        inp + (size_t)(b * PSLOTS + slot) * PN * 2)[l * PK + kk];
    const float q2 = fmaf(pt.x, pt.x, pt.y * pt.y);
    const float rr = 1.0f / (1.0f + sqrtf(1.0f + q2));
    const float p0 = pt.x * rr;
    const float p1 = pt.y * rr;
    const float ps = fmaf(p0, p0, p1 * p1);

    const float ps2 = ps * ps, ps3 = ps2 * ps;
    const float a2 = p0 * p0, a3 = a2 * p0, a4 = a2 * a2;
    const float b2 = p1 * p1, b3v = b2 * p1, b4 = b2 * b2;
    const float ab = p0 * p1;
    float v[34];
    v[0] = ps;        v[1] = p0;        v[2] = p1;
    v[3] = ps2;       v[4] = ps * p0;   v[5] = ps * p1;
    v[6] = a2;        v[7] = ab;        v[8] = b2;
    v[9] = ps3;       v[10] = ps2 * p0; v[11] = ps2 * p1;
    v[12] = ps * a2;  v[13] = ps * ab;  v[14] = ps * b2;
    v[15] = a3;       v[16] = a2 * p1;  v[17] = p0 * b2;  v[18] = b3v;
    v[19] = ps3 * p0; v[20] = ps2 * a2; v[21] = ps2 * ab;
    v[22] = ps * a3;  v[23] = ps * v[16]; v[24] = ps * v[17];
    v[25] = a4;       v[26] = a3 * p1;  v[27] = a2 * b2;  v[28] = p0 * b3v;
    v[29] = ps3 * p1; v[30] = ps2 * b2; v[31] = ps * b3v; v[32] = b4;
    v[33] = 0.0f;

    // ---- split-shuffle reduction over the 16-lane half-warp ----
    float w8[18];
    #pragma unroll
    for (int k = 0; k < 17; ++k) {
        const float send = (lane & 8) ? v[k] : v[17 + k];
        const float recv = __shfl_xor_sync(0xffffffffu, send, 8);
        w8[k] = ((lane & 8) ? v[17 + k] : v[k]) + recv;
    }
    w8[17] = 0.0f;
    float x4[10];
    #pragma unroll
    for (int k = 0; k < 9; ++k) {
        const float send = (lane & 4) ? w8[k] : w8[9 + k];
        const float recv = __shfl_xor_sync(0xffffffffu, send, 4);
        x4[k] = ((lane & 4) ? w8[9 + k] : w8[k]) + recv;
    }
    x4[9] = 0.0f;
    float z5[5];
    #pragma unroll
    for (int k = 0; k < 5; ++k) {
        const float send = (lane & 2) ? x4[k] : x4[5 + k];
        const float recv = __shfl_xor_sync(0xffffffffu, send, 2);
        z5[k] = ((lane & 2) ? x4[5 + k] : x4[k]) + recv;
    }
    #pragma unroll
    for (int k = 0; k < 5; ++k)
        z5[k] += __shfl_xor_sync(0xffffffffu, z5[k], 1);

    // ---- store moments (even lanes), slot base from lane bits ----
    if (!(lane & 1)) {
        const int base = ((lane >> 1) & 7) * 5;
        #pragma unroll
        for (int k = 0; k < 5; ++k) {
            float val = z5[k];
            if (base + k == 37) val = 16.0f;   // constant moment M[0,0,0]
            sMom[kkL][base + k] = val;
        }
    }

    // ---- gate on K1's gC, then warp-local matvec straight from L2 ----
#if __CUDA_ARCH__ >= 900
    cudaGridDependencySynchronize();
#endif
    __syncwarp();

    const int j = lane & 15;                    // job id within half-warp
    if (j < 12) {
        const float* col = &gC[slot][0][j];     // stride 12 floats
        const float* mom = sMom[kkL];
        float acc0 = 0.0f, acc1 = 0.0f;
        #pragma unroll
        for (int ms = 0; ms < 38; ms += 2) {
            acc0 = fmaf(mom[ms],     col[ms * 12],      acc0);
            acc1 = fmaf(mom[ms + 1], col[ms * 12 + 12], acc1);
        }
        sS[kkL][j] = acc0 + acc1;
    }
    __syncwarp();

    // ---- epilogue: out = OS_CONST * s / ||s|| ----
    if ((lane & 15) == 0) {
        const float* sv = sS[kkL];
        const float s0 = sv[0] + sv[10];
        const float s1 = sv[1] + sv[11];
        float dot = fmaf(s0, s0, s1 * s1);
        #pragma unroll
        for (int d = 2; d < 10; ++d)
            dot = fmaf(sv[d], sv[d], dot);
        const float cm = OS_CONST * rsqrtf(dot);

        float* op = out + (size_t)((b * PSLOTS + slot) * PK + kk) * PD;
        float2* o2 = reinterpret_cast<float2*>(op);
        o2[0] = make_float2(cm * s0,    cm * s1);
        o2[1] = make_float2(cm * sv[2], cm * sv[3]);
        o2[2] = make_float2(cm * sv[4], cm * sv[5]);
        o2[3] = make_float2(cm * sv[6], cm * sv[7]);
        o2[4] = make_float2(cm * sv[8], cm * sv[9]);
    }
}

extern "C" void kernel_launch(void* const* d_in, const int* in_sizes, int n_in,
                              void* d_out, int out_size) {
    const float* inp   = (const float*)d_in[0];
    const float* theta = (const float*)d_in[1];
    if (n_in >= 2 && in_sizes[0] == PSLOTS * PK * PD) {
        inp   = (const float*)d_in[1];
        theta = (const float*)d_in[0];
    }
    float* out = (float*)d_out;

    pman_coef_kernel<<<110, 128>>>(theta);          // 440 warps

    // K2 with Programmatic Stream Serialization: front phase overlaps K1.
    cudaLaunchConfig_t cfg = {};
    cfg.gridDim  = dim3(8, PSLOTS, PB);             // 512 blocks
    cfg.blockDim = dim3(128, 1, 1);
    cudaLaunchAttribute attrs[1];
    attrs[0].id = cudaLaunchAttributeProgrammaticStreamSerialization;
    attrs[0].val.programmaticStreamSerializationAllowed = 1;
    cfg.attrs = attrs;
    cfg.numAttrs = 1;
    cudaLaunchKernelEx(&cfg, pman_main_kernel, inp, out);
}